// round 1
// baseline (speedup 1.0000x reference)
#include <cuda_runtime.h>

// Scalar DCP reduction:
// result = sum_{b,r,c} w(r)*w(c)*|min over 3 channels of x[b,ch,r,c]|
// with w = 2 at index 0 or 1023, else 3. (Derived from pad+3x3 window sum:
// each padded pixel is counted once per covering window; zero padding
// contributes |min(0,0,0)|=0.)

#define B   16
#define H   1024
#define Wd  1024
#define W4  256           // Wd / 4
#define CH  (1024LL*1024LL)   // channel stride in floats

__device__ double g_acc;

__global__ void dcp_zero_kernel() { g_acc = 0.0; }

__global__ __launch_bounds__(256) void dcp_main_kernel(const float* __restrict__ x) {
    const long long N4 = (long long)B * H * W4;   // 4,194,304 vec4 positions
    float tsum = 0.f;

    for (long long i = (long long)blockIdx.x * blockDim.x + threadIdx.x;
         i < N4;
         i += (long long)gridDim.x * blockDim.x) {
        int c4 = (int)(i & (W4 - 1));
        long long t = i >> 8;          // / W4
        int r = (int)(t & (H - 1));
        long long b = t >> 10;         // / H

        const float* base = x + b * 3 * CH + (long long)r * Wd + (long long)c4 * 4;
        float4 a0 = *(const float4*)(base);
        float4 a1 = *(const float4*)(base + CH);
        float4 a2 = *(const float4*)(base + 2 * CH);

        float m0 = fabsf(fminf(fminf(a0.x, a1.x), a2.x));
        float m1 = fabsf(fminf(fminf(a0.y, a1.y), a2.y));
        float m2 = fabsf(fminf(fminf(a0.z, a1.z), a2.z));
        float m3 = fabsf(fminf(fminf(a0.w, a1.w), a2.w));

        float wr = (r == 0 || r == H - 1) ? 2.f : 3.f;
        int c0 = c4 * 4;
        float w0 = (c0 == 0) ? 2.f : 3.f;          // only first vec of a row
        float w3 = (c0 + 3 == Wd - 1) ? 2.f : 3.f; // only last vec of a row

        tsum += wr * (w0 * m0 + 3.f * m1 + 3.f * m2 + w3 * m3);
    }

    // warp reduction
    #pragma unroll
    for (int ofs = 16; ofs > 0; ofs >>= 1)
        tsum += __shfl_xor_sync(0xFFFFFFFFu, tsum, ofs);

    __shared__ float warp_sums[8];
    int lane = threadIdx.x & 31;
    int wid  = threadIdx.x >> 5;
    if (lane == 0) warp_sums[wid] = tsum;
    __syncthreads();

    if (wid == 0) {
        float v = (lane < 8) ? warp_sums[lane] : 0.f;
        #pragma unroll
        for (int ofs = 4; ofs > 0; ofs >>= 1)
            v += __shfl_xor_sync(0xFFFFFFFFu, v, ofs);
        if (lane == 0)
            atomicAdd(&g_acc, (double)v);
    }
}

__global__ void dcp_finalize_kernel(float* out) { out[0] = (float)g_acc; }

extern "C" void kernel_launch(void* const* d_in, const int* in_sizes, int n_in,
                              void* d_out, int out_size) {
    const float* x = (const float*)d_in[0];
    float* out = (float*)d_out;

    dcp_zero_kernel<<<1, 1>>>();
    // 148 SMs; plenty of blocks for full occupancy + load balance
    dcp_main_kernel<<<148 * 24, 256>>>(x);
    dcp_finalize_kernel<<<1, 1>>>(out);
}